// round 16
// baseline (speedup 1.0000x reference)
#include <cuda_runtime.h>

#define NN   50000
#define EE   500000
#define EMBD 50
#define EMBP 52
#define C1   256
#define C2   50
#define ED   28
#define TE   32
#define TE2  32

static __device__ float  g_xl[(size_t)NN * C1];
static __device__ float  g_xr[(size_t)NN * C1];
static __device__ float  g_h1[(size_t)NN * C1];
static __device__ float  g_logit[(size_t)EE];
static __device__ float  g_den[(size_t)5 * NN];
static __device__ int    g_off[NN + 1];
static __device__ int    g_cur[NN];
static __device__ int    g_eid[EE];
static __device__ int    g_esrc[EE];
static __device__ int    g_edst[EE];
static __device__ float  g_o2[(size_t)NN * C2];
static __device__ double g_red[4];

__device__ __forceinline__ float lrelu(float v) { return v > 0.f ? v : 0.2f * v; }

// ---- packed f32x2 helpers ----
__device__ __forceinline__ unsigned long long fma2(unsigned long long a,
                                                   unsigned long long b,
                                                   unsigned long long c) {
    unsigned long long d;
    asm("fma.rn.f32x2 %0, %1, %2, %3;" : "=l"(d) : "l"(a), "l"(b), "l"(c));
    return d;
}
__device__ __forceinline__ unsigned long long pack2(float x, float y) {
    unsigned long long d;
    asm("mov.b64 %0, {%1, %2};" : "=l"(d) : "r"(__float_as_int(x)), "r"(__float_as_int(y)));
    return d;
}
__device__ __forceinline__ float2 unpack2(unsigned long long v) {
    int lo, hi;
    asm("mov.b64 {%0, %1}, %2;" : "=r"(lo), "=r"(hi) : "l"(v));
    return make_float2(__int_as_float(lo), __int_as_float(hi));
}

__global__ void k_init() {
    int i = blockIdx.x * blockDim.x + threadIdx.x;
    if (i < NN * C1) g_h1[i] = 0.f;
    if (i < 5 * NN) g_den[i] = 0.f;
    if (i < NN) g_cur[i] = 0;
    if (i < 4)  g_red[i] = 0.0;
}

__global__ void k_deg(const int* __restrict__ ei) {
    int e = blockIdx.x * blockDim.x + threadIdx.x;
    if (e < EE) atomicAdd(&g_cur[ei[EE + e]], 1);
}

// coalesced single-block scan through 200KB smem
__global__ void k_scan() {
    extern __shared__ int si[];
    int t = threadIdx.x;
    for (int i = t; i < NN; i += 1024) si[i] = g_cur[i];
    __syncthreads();
    const int CH = (NN + 1023) / 1024;
    int lane = t & 31, w = t >> 5;
    int beg = t * CH;
    int end = beg + CH; if (end > NN) end = NN;
    int s = 0;
    for (int i = beg; i < end; i++) s += si[i];
    int incl = s;
#pragma unroll
    for (int off = 1; off < 32; off <<= 1) {
        int y = __shfl_up_sync(0xffffffffu, incl, off);
        if (lane >= off) incl += y;
    }
    __shared__ int ws[32];
    if (lane == 31) ws[w] = incl;
    __syncthreads();
    if (w == 0) {
        int v = ws[lane];
#pragma unroll
        for (int off = 1; off < 32; off <<= 1) {
            int y = __shfl_up_sync(0xffffffffu, v, off);
            if (lane >= off) v += y;
        }
        ws[lane] = v;
    }
    __syncthreads();
    int run = incl - s + (w > 0 ? ws[w - 1] : 0);
    for (int i = beg; i < end; i++) {
        int v = si[i];
        si[i] = run;
        run += v;
    }
    __syncthreads();
    for (int i = t; i < NN; i += 1024) {
        int v = si[i];
        g_off[i] = v;
        g_cur[i] = v;
    }
    if (t == 0) g_off[NN] = ws[31];
}

__global__ void k_fill(const int* __restrict__ ei) {
    int e = blockIdx.x * blockDim.x + threadIdx.x;
    if (e < EE) {
        int d = ei[EE + e];
        int pos = atomicAdd(&g_cur[d], 1);
        g_eid[pos]  = e;
        g_esrc[pos] = ei[e];
        g_edst[pos] = d;
    }
}

// node transform L1: gridDim.y=2 selects (Wl,bl)->xl vs (Wr,br)->xr
__global__ __launch_bounds__(256) void k_node1(const int* __restrict__ x,
                                               const float* __restrict__ emb,
                                               const float* __restrict__ Wl,
                                               const float* __restrict__ bl,
                                               const float* __restrict__ Wr,
                                               const float* __restrict__ br) {
    extern __shared__ float sm[];
    float* s_w  = sm;
    float* s_h2 = sm + EMBP * C1;
    __shared__ int xs[32];
    int sel = blockIdx.y;
    const float* W    = sel ? Wr : Wl;
    const float* bvec = sel ? br : bl;
    int t = threadIdx.x;
    int nb = blockIdx.x * 32;
    if (t < 32) xs[t] = (nb + t < NN) ? x[nb + t] : 0;
    for (int i = t; i < EMBD * C1 / 4; i += 256)
        ((float4*)s_w)[i] = ((const float4*)W)[i];
    for (int i = t; i < (EMBP - EMBD) * C1 / 4; i += 256)
        ((float4*)s_w)[EMBD * C1 / 4 + i] = make_float4(0.f, 0.f, 0.f, 0.f);
    __syncthreads();
    for (int i = t; i < 32 * EMBP; i += 256) {
        int n = i / EMBP, k = i % EMBP;
        float v = (k < EMBD) ? emb[(size_t)xs[n] * EMBD + k] : 0.f;
        s_h2[i * 2] = v; s_h2[i * 2 + 1] = v;
    }
    __syncthreads();
    int cg = t & 63, g = t >> 6;
    int c0 = cg * 4;
    float4 bv = *(const float4*)&bvec[c0];
    ulonglong2 acc[8];
#pragma unroll
    for (int j = 0; j < 8; j++) {
        acc[j].x = pack2(bv.x, bv.y);
        acc[j].y = pack2(bv.z, bv.w);
    }
#pragma unroll 4
    for (int k = 0; k < EMBP; k++) {
        ulonglong2 w = *(const ulonglong2*)&s_w[k * C1 + c0];
#pragma unroll
        for (int j = 0; j < 8; j++) {
            unsigned long long h2 =
                *(const unsigned long long*)&s_h2[((g * 8 + j) * EMBP + k) * 2];
            acc[j].x = fma2(h2, w.x, acc[j].x);
            acc[j].y = fma2(h2, w.y, acc[j].y);
        }
    }
    float* dst = sel ? g_xr : g_xl;
#pragma unroll
    for (int j = 0; j < 8; j++) {
        int n = nb + g * 8 + j;
        if (n < NN) {
            float2 lo = unpack2(acc[j].x), hi = unpack2(acc[j].y);
            *(float4*)&dst[(size_t)n * C1 + c0] = make_float4(lo.x, lo.y, hi.x, hi.y);
        }
    }
}

// edge logits L1 + FUSED aggregation: computes ex, den, and run-segmented
// atomic accumulation of ex*xl[src] into g_h1 (CSR dst runs -> few flushes)
__global__ __launch_bounds__(256, 4) void k_edge1(const float* __restrict__ ea,
                                                  const float* __restrict__ We,
                                                  const float* __restrict__ att) {
    extern __shared__ float sm[];
    float* s_we  = sm;                      // 28*256 = 7168 floats
    float* s_ea2 = sm + 7168;               // 32*28*2 = 1792 floats
    __shared__ int s_src[TE], s_dst[TE], s_eid[TE];
    __shared__ float s_ex[TE * 4];
    int t  = threadIdx.x;
    int eb = blockIdx.x * TE;
    if (t < TE) {
        s_src[t] = g_esrc[eb + t];
        s_dst[t] = g_edst[eb + t];
        s_eid[t] = g_eid[eb + t];
    }
    for (int i = t; i < ED * C1 / 4; i += 256)
        ((float4*)s_we)[i] = ((const float4*)We)[i];
    __syncthreads();
    for (int i = t; i < TE * ED; i += 256) {
        int e = i / ED, k = i - e * ED;
        float v = ea[(size_t)s_eid[e] * ED + k];
        s_ea2[i * 2] = v; s_ea2[i * 2 + 1] = v;
    }
    int cg = t & 63, eq = t >> 6;
    int c0 = cg * 4;
    ulonglong2 acc[8];
#pragma unroll
    for (int j = 0; j < 8; j++) {
        int e = eq * 8 + j;
        float4 a = *(const float4*)&g_xl[(size_t)s_src[e] * C1 + c0];
        float4 b = *(const float4*)&g_xr[(size_t)s_dst[e] * C1 + c0];
        acc[j].x = pack2(a.x + b.x, a.y + b.y);
        acc[j].y = pack2(a.z + b.z, a.w + b.w);
    }
    __syncthreads();
#pragma unroll 4
    for (int k = 0; k < ED; k++) {
        ulonglong2 w = *(const ulonglong2*)&s_we[k * C1 + c0];
#pragma unroll
        for (int j = 0; j < 8; j++) {
            unsigned long long e2 =
                *(const unsigned long long*)&s_ea2[((eq * 8 + j) * ED + k) * 2];
            acc[j].x = fma2(e2, w.x, acc[j].x);
            acc[j].y = fma2(e2, w.y, acc[j].y);
        }
    }
    float a0 = att[c0], a1 = att[c0 + 1], a2 = att[c0 + 2], a3 = att[c0 + 3];
    float part[8];
#pragma unroll
    for (int j = 0; j < 8; j++) {
        float2 lo = unpack2(acc[j].x), hi = unpack2(acc[j].y);
        part[j] = lrelu(lo.x) * a0 + lrelu(lo.y) * a1 +
                  lrelu(hi.x) * a2 + lrelu(hi.y) * a3;
    }
#pragma unroll
    for (int off = 8; off; off >>= 1) {
#pragma unroll
        for (int j = 0; j < 8; j++)
            part[j] += __shfl_down_sync(0xffffffffu, part[j], off);
    }
    int lane = t & 31;
    int h = cg >> 4;
    if ((lane & 15) == 0) {
#pragma unroll
        for (int j = 0; j < 8; j++) {
            int e = eq * 8 + j;
            float ex = expf(part[j]);
            s_ex[e * 4 + h] = ex;
            atomicAdd(&g_den[s_dst[e] * 4 + h], ex);
        }
    }
    __syncthreads();
    // fused aggregation: run-segmented over CSR dst runs, atomic flush per run
    float4 aggr = make_float4(0.f, 0.f, 0.f, 0.f);
    int cur = s_dst[eq * 8];
#pragma unroll
    for (int j = 0; j < 8; j++) {
        int e = eq * 8 + j;
        int d = s_dst[e];
        if (d != cur) {
            float* dp = &g_h1[(size_t)cur * C1 + c0];
            atomicAdd(dp + 0, aggr.x); atomicAdd(dp + 1, aggr.y);
            atomicAdd(dp + 2, aggr.z); atomicAdd(dp + 3, aggr.w);
            aggr = make_float4(0.f, 0.f, 0.f, 0.f);
            cur = d;
        }
        float ex = s_ex[e * 4 + h];
        float4 v = *(const float4*)&g_xl[(size_t)s_src[e] * C1 + c0];
        aggr.x += ex * v.x; aggr.y += ex * v.y;
        aggr.z += ex * v.z; aggr.w += ex * v.w;
    }
    float* dp = &g_h1[(size_t)cur * C1 + c0];
    atomicAdd(dp + 0, aggr.x); atomicAdd(dp + 1, aggr.y);
    atomicAdd(dp + 2, aggr.z); atomicAdd(dp + 3, aggr.w);
}

// normalize L1: h1 = h1/den + bias, fused LN stats
__global__ __launch_bounds__(256) void k_norm1(const float* __restrict__ bias) {
    int stride = gridDim.x * blockDim.x;
    double s = 0.0, q = 0.0;
    for (int i = blockIdx.x * blockDim.x + threadIdx.x; i < NN * C1; i += stride) {
        int n = i >> 8;
        int c = i & 255;
        int h = c >> 6;
        float o = g_h1[i] / (g_den[n * 4 + h] + 1e-16f) + bias[c];
        g_h1[i] = o;
        s += (double)o; q += (double)o * o;
    }
#pragma unroll
    for (int off = 16; off; off >>= 1) {
        s += __shfl_down_sync(0xffffffffu, s, off);
        q += __shfl_down_sync(0xffffffffu, q, off);
    }
    __shared__ double sh[8], qh[8];
    int lane = threadIdx.x & 31, w = threadIdx.x >> 5;
    if (lane == 0) { sh[w] = s; qh[w] = q; }
    __syncthreads();
    if (threadIdx.x == 0) {
        double S = 0.0, Q = 0.0;
        for (int i = 0; i < 8; i++) { S += sh[i]; Q += qh[i]; }
        atomicAdd(&g_red[0], S); atomicAdd(&g_red[1], Q);
    }
}

// node transform L2: fused LN1+ReLU, duplicated-h smem, f32x2
__global__ __launch_bounds__(256) void k_node2(const float* __restrict__ Wl,
                                               const float* __restrict__ bl,
                                               const float* __restrict__ Wr,
                                               const float* __restrict__ br,
                                               const float* __restrict__ lnw,
                                               const float* __restrict__ lnb) {
    __shared__ float hs2[16 * C1 * 2];
    __shared__ float s_lnw[C1], s_lnb[C1];
    __shared__ float s_mf[2];
    int t = threadIdx.x;
    int nb = blockIdx.x * 16;
    if (t < C1) { s_lnw[t] = lnw[t]; s_lnb[t] = lnb[t]; }
    if (t == 0) {
        double M = (double)NN * C1;
        double mean = g_red[0] / M;
        double var  = g_red[1] / M - mean * mean;
        s_mf[0] = (float)mean;
        s_mf[1] = 1.f / ((float)sqrt(var > 0.0 ? var : 0.0) + 1e-5f);
    }
    __syncthreads();
    float mean = s_mf[0], f = s_mf[1];
    for (int i = t; i < 16 * C1 / 4; i += 256) {
        float4 v = *(const float4*)&g_h1[(size_t)nb * C1 + (size_t)i * 4];
        int k = (i & 63) * 4;
        float4 w4 = *(const float4*)&s_lnw[k];
        float4 b4 = *(const float4*)&s_lnb[k];
        v.x = (v.x - mean) * f * w4.x + b4.x; v.x = v.x > 0.f ? v.x : 0.f;
        v.y = (v.y - mean) * f * w4.y + b4.y; v.y = v.y > 0.f ? v.y : 0.f;
        v.z = (v.z - mean) * f * w4.z + b4.z; v.z = v.z > 0.f ? v.z : 0.f;
        v.w = (v.w - mean) * f * w4.w + b4.w; v.w = v.w > 0.f ? v.w : 0.f;
        *(float4*)&hs2[i * 8]     = make_float4(v.x, v.x, v.y, v.y);
        *(float4*)&hs2[i * 8 + 4] = make_float4(v.z, v.z, v.w, v.w);
    }
    __syncthreads();
    int cp = t & 31;
    int c2 = cp * 2;
    int grp = t >> 5;
    int n0 = grp * 2, n1 = grp * 2 + 1;
    bool act = (c2 + 1) < C2;
    unsigned long long blv = 0, brv = 0;
    if (act) {
        blv = pack2(bl[c2], bl[c2 + 1]);
        brv = pack2(br[c2], br[c2 + 1]);
    }
    unsigned long long al0 = blv, al1 = blv, ar0 = brv, ar1 = brv;
#pragma unroll 4
    for (int k = 0; k < C1; k++) {
        unsigned long long wl = 0, wr = 0;
        if (act) {
            wl = *(const unsigned long long*)&Wl[k * C2 + c2];
            wr = *(const unsigned long long*)&Wr[k * C2 + c2];
        }
        unsigned long long h0 = *(const unsigned long long*)&hs2[(n0 * C1 + k) * 2];
        unsigned long long h1 = *(const unsigned long long*)&hs2[(n1 * C1 + k) * 2];
        al0 = fma2(h0, wl, al0);
        al1 = fma2(h1, wl, al1);
        ar0 = fma2(h0, wr, ar0);
        ar1 = fma2(h1, wr, ar1);
    }
    if (act) {
        float2 v;
        v = unpack2(al0); *(float2*)&g_xl[(size_t)(nb + n0) * C2 + c2] = v;
        v = unpack2(al1); *(float2*)&g_xl[(size_t)(nb + n1) * C2 + c2] = v;
        v = unpack2(ar0); *(float2*)&g_xr[(size_t)(nb + n0) * C2 + c2] = v;
        v = unpack2(ar1); *(float2*)&g_xr[(size_t)(nb + n1) * C2 + c2] = v;
    }
}

// edge logits L2, CSR order: block-tile, smem ea splats, f32x2
__global__ __launch_bounds__(256, 4) void k_edge2(const float* __restrict__ ea,
                                                  const float* __restrict__ We,
                                                  const float* __restrict__ att) {
    __shared__ float s_we2[ED * 64];
    __shared__ float s_ea2[TE2 * ED * 2];
    __shared__ float s_att[64];
    __shared__ int s_src[TE2], s_dst[TE2], s_eid[TE2];
    int t = threadIdx.x;
    int eb = blockIdx.x * TE2;
    if (t < TE2) {
        s_src[t] = g_esrc[eb + t];
        s_dst[t] = g_edst[eb + t];
        s_eid[t] = g_eid[eb + t];
    }
    if (t < 64) s_att[t] = (t < C2) ? att[t] : 0.f;
    for (int i = t; i < ED * 64; i += 256) {
        int k = i >> 6, c = i & 63;
        s_we2[i] = (c < C2) ? We[k * C2 + c] : 0.f;
    }
    __syncthreads();
    for (int i = t; i < TE2 * ED; i += 256) {
        int e = i / ED, k = i - e * ED;
        float v = ea[(size_t)s_eid[e] * ED + k];
        s_ea2[i * 2] = v; s_ea2[i * 2 + 1] = v;
    }
    int cg = t & 31, eq = t >> 5;
    int c0 = cg * 2;
    bool act = c0 < C2;
    unsigned long long acc[4];
#pragma unroll
    for (int j = 0; j < 4; j++) {
        int e = eq * 4 + j;
        float mx = 0.f, my = 0.f;
        if (act) {
            float2 u = *(const float2*)&g_xl[(size_t)s_src[e] * C2 + c0];
            float2 v = *(const float2*)&g_xr[(size_t)s_dst[e] * C2 + c0];
            mx = u.x + v.x; my = u.y + v.y;
        }
        acc[j] = pack2(mx, my);
    }
    __syncthreads();
#pragma unroll 4
    for (int k = 0; k < ED; k++) {
        unsigned long long w2 = *(const unsigned long long*)&s_we2[k * 64 + c0];
#pragma unroll
        for (int j = 0; j < 4; j++) {
            unsigned long long e2 =
                *(const unsigned long long*)&s_ea2[((eq * 4 + j) * ED + k) * 2];
            acc[j] = fma2(e2, w2, acc[j]);
        }
    }
    float2 a2 = *(const float2*)&s_att[c0];
    float part[4];
#pragma unroll
    for (int j = 0; j < 4; j++) {
        float2 m = unpack2(acc[j]);
        part[j] = lrelu(m.x) * a2.x + lrelu(m.y) * a2.y;
    }
#pragma unroll
    for (int off = 16; off; off >>= 1) {
#pragma unroll
        for (int j = 0; j < 4; j++)
            part[j] += __shfl_down_sync(0xffffffffu, part[j], off);
    }
    if (cg == 0) {
#pragma unroll
        for (int j = 0; j < 4; j++) {
            int e = eq * 4 + j;
            float ex = expf(part[j]);
            g_logit[eb + e] = ex;
            atomicAdd(&g_den[4 * NN + s_dst[e]], ex);
        }
    }
}

// aggregation L2: pure weighted gather + fused LN stats
__global__ __launch_bounds__(256) void k_agg2(const float* __restrict__ bias) {
    int t = threadIdx.x;
    int n = blockIdx.x * 4 + (t >> 6);
    int t64 = t & 63;
    int lane = t & 31;
    int s = g_off[n], en = g_off[n + 1];
    bool act = t64 < C2;
    float acc = 0.f;
    for (int p = s; p < en; p++) {
        float ex = g_logit[p];
        int src = g_esrc[p];
        if (act) acc += ex * g_xl[(size_t)src * C2 + t64];
    }
    float o = 0.f;
    if (act) {
        o = acc / (g_den[4 * NN + n] + 1e-16f) + bias[t64];
        g_o2[(size_t)n * C2 + t64] = o;
    }
    float sv = o, qv = o * o;
#pragma unroll
    for (int off = 16; off; off >>= 1) {
        sv += __shfl_down_sync(0xffffffffu, sv, off);
        qv += __shfl_down_sync(0xffffffffu, qv, off);
    }
    __shared__ double sh[8], qh[8];
    int w = t >> 5;
    if (lane == 0) { sh[w] = (double)sv; qh[w] = (double)qv; }
    __syncthreads();
    if (t == 0) {
        double S = 0.0, Q = 0.0;
        for (int i = 0; i < 8; i++) { S += sh[i]; Q += qh[i]; }
        atomicAdd(&g_red[2], S); atomicAdd(&g_red[3], Q);
    }
}

__global__ void k_ln2(float* __restrict__ out, const float* __restrict__ w,
                      const float* __restrict__ b) {
    int i = blockIdx.x * blockDim.x + threadIdx.x;
    if (i < NN * C2) {
        double M = (double)NN * C2;
        double mean = g_red[2] / M;
        double var  = g_red[3] / M - mean * mean;
        float f = 1.f / ((float)sqrt(var > 0.0 ? var : 0.0) + 1e-5f);
        int c = i % C2;
        out[i] = (g_o2[i] - (float)mean) * f * w[c] + b[c];
    }
}

extern "C" void kernel_launch(void* const* d_in, const int* in_sizes, int n_in,
                              void* d_out, int out_size) {
    const int*   x    = (const int*)d_in[0];
    const int*   ei   = (const int*)d_in[1];
    const float* ea   = (const float*)d_in[2];
    const float* emb  = (const float*)d_in[3];
    const float* Wl1  = (const float*)d_in[4];
    const float* bl1  = (const float*)d_in[5];
    const float* Wr1  = (const float*)d_in[6];
    const float* br1  = (const float*)d_in[7];
    const float* We1  = (const float*)d_in[8];
    const float* att1 = (const float*)d_in[9];
    const float* bias1= (const float*)d_in[10];
    const float* ln1w = (const float*)d_in[11];
    const float* ln1b = (const float*)d_in[12];
    const float* Wl2  = (const float*)d_in[13];
    const float* bl2  = (const float*)d_in[14];
    const float* Wr2  = (const float*)d_in[15];
    const float* br2  = (const float*)d_in[16];
    const float* We2  = (const float*)d_in[17];
    const float* att2 = (const float*)d_in[18];
    const float* bias2= (const float*)d_in[19];
    const float* ln2w = (const float*)d_in[20];
    const float* ln2b = (const float*)d_in[21];
    float* out = (float*)d_out;

    const int node1_smem = (EMBP * C1 + 32 * EMBP * 2) * 4;   // ~66.6 KB
    const int edge1_smem = (7168 + TE * ED * 2) * 4;          // ~35.8 KB
    const int scan_smem  = NN * 4;                            // 200 KB
    cudaFuncSetAttribute(k_node1, cudaFuncAttributeMaxDynamicSharedMemorySize, node1_smem);
    cudaFuncSetAttribute(k_edge1, cudaFuncAttributeMaxDynamicSharedMemorySize, edge1_smem);
    cudaFuncSetAttribute(k_scan,  cudaFuncAttributeMaxDynamicSharedMemorySize, scan_smem);

    dim3 n1grid((NN + 31) / 32, 2);

    k_init<<<(NN * C1 + 255) / 256, 256>>>();                              // 1
    k_deg<<<(EE + 255) / 256, 256>>>(ei);                                  // 2
    k_scan<<<1, 1024, scan_smem>>>();                                      // 3
    k_node1<<<n1grid, 256, node1_smem>>>(x, emb, Wl1, bl1, Wr1, br1);      // 4 <- profiled
    k_fill<<<(EE + 255) / 256, 256>>>(ei);                                 // 5
    k_edge1<<<EE / TE, 256, edge1_smem>>>(ea, We1, att1);                  // 6
    k_norm1<<<2048, 256>>>(bias1);                                         // 7
    k_node2<<<NN / 16, 256>>>(Wl2, bl2, Wr2, br2, ln1w, ln1b);             // 8
    k_edge2<<<EE / TE2, 256>>>(ea, We2, att2);                             // 9
    k_agg2<<<NN / 4, 256>>>(bias2);                                        // 10
    k_ln2<<<(NN * C2 + 255) / 256, 256>>>(out, ln2w, ln2b);                // 11
}

// round 17
// speedup vs baseline: 1.0841x; 1.0841x over previous
#include <cuda_runtime.h>

#define NN   50000
#define EE   500000
#define EMBD 50
#define EMBP 52
#define C1   256
#define C2   50
#define ED   28
#define TE   32
#define TE2  32

static __device__ float  g_xl[(size_t)NN * C1];
static __device__ float  g_xr[(size_t)NN * C1];
static __device__ float  g_h1[(size_t)NN * C1];
static __device__ float  g_logit[(size_t)EE * 4];
static __device__ float  g_den[(size_t)5 * NN];
static __device__ int    g_off[NN + 1];
static __device__ int    g_cur[NN];
static __device__ int4   g_epk[EE];          // {eid, src, dst, pad}
static __device__ float  g_o2[(size_t)NN * C2];
static __device__ double g_red[4];

__device__ __forceinline__ float lrelu(float v) { return v > 0.f ? v : 0.2f * v; }

// ---- packed f32x2 helpers ----
__device__ __forceinline__ unsigned long long fma2(unsigned long long a,
                                                   unsigned long long b,
                                                   unsigned long long c) {
    unsigned long long d;
    asm("fma.rn.f32x2 %0, %1, %2, %3;" : "=l"(d) : "l"(a), "l"(b), "l"(c));
    return d;
}
__device__ __forceinline__ unsigned long long pack2(float x, float y) {
    unsigned long long d;
    asm("mov.b64 %0, {%1, %2};" : "=l"(d) : "r"(__float_as_int(x)), "r"(__float_as_int(y)));
    return d;
}
__device__ __forceinline__ float2 unpack2(unsigned long long v) {
    int lo, hi;
    asm("mov.b64 {%0, %1}, %2;" : "=r"(lo), "=r"(hi) : "l"(v));
    return make_float2(__int_as_float(lo), __int_as_float(hi));
}

__global__ void k_init() {
    int i = blockIdx.x * blockDim.x + threadIdx.x;
    if (i < 5 * NN) g_den[i] = 0.f;
    if (i < NN) g_cur[i] = 0;
    if (i < 4)  g_red[i] = 0.0;
}

__global__ void k_deg(const int* __restrict__ ei) {
    int e = blockIdx.x * blockDim.x + threadIdx.x;
    if (e < EE) atomicAdd(&g_cur[ei[EE + e]], 1);
}

// coalesced single-block scan through 200KB smem
__global__ void k_scan() {
    extern __shared__ int si[];
    int t = threadIdx.x;
    for (int i = t; i < NN; i += 1024) si[i] = g_cur[i];
    __syncthreads();
    const int CH = (NN + 1023) / 1024;
    int lane = t & 31, w = t >> 5;
    int beg = t * CH;
    int end = beg + CH; if (end > NN) end = NN;
    int s = 0;
    for (int i = beg; i < end; i++) s += si[i];
    int incl = s;
#pragma unroll
    for (int off = 1; off < 32; off <<= 1) {
        int y = __shfl_up_sync(0xffffffffu, incl, off);
        if (lane >= off) incl += y;
    }
    __shared__ int ws[32];
    if (lane == 31) ws[w] = incl;
    __syncthreads();
    if (w == 0) {
        int v = ws[lane];
#pragma unroll
        for (int off = 1; off < 32; off <<= 1) {
            int y = __shfl_up_sync(0xffffffffu, v, off);
            if (lane >= off) v += y;
        }
        ws[lane] = v;
    }
    __syncthreads();
    int run = incl - s + (w > 0 ? ws[w - 1] : 0);
    for (int i = beg; i < end; i++) {
        int v = si[i];
        si[i] = run;
        run += v;
    }
    __syncthreads();
    for (int i = t; i < NN; i += 1024) {
        int v = si[i];
        g_off[i] = v;
        g_cur[i] = v;
    }
    if (t == 0) g_off[NN] = ws[31];
}

__global__ void k_fill(const int* __restrict__ ei) {
    int e = blockIdx.x * blockDim.x + threadIdx.x;
    if (e < EE) {
        int src = ei[e];
        int d   = ei[EE + e];
        int pos = atomicAdd(&g_cur[d], 1);
        g_epk[pos] = make_int4(e, src, d, 0);
    }
}

// node transform L1: gridDim.y=2 selects (Wl,bl)->xl vs (Wr,br)->xr
__global__ __launch_bounds__(256) void k_node1(const int* __restrict__ x,
                                               const float* __restrict__ emb,
                                               const float* __restrict__ Wl,
                                               const float* __restrict__ bl,
                                               const float* __restrict__ Wr,
                                               const float* __restrict__ br) {
    extern __shared__ float sm[];
    float* s_w  = sm;
    float* s_h2 = sm + EMBP * C1;
    __shared__ int xs[32];
    int sel = blockIdx.y;
    const float* W    = sel ? Wr : Wl;
    const float* bvec = sel ? br : bl;
    int t = threadIdx.x;
    int nb = blockIdx.x * 32;
    if (t < 32) xs[t] = (nb + t < NN) ? x[nb + t] : 0;
    for (int i = t; i < EMBD * C1 / 4; i += 256)
        ((float4*)s_w)[i] = ((const float4*)W)[i];
    for (int i = t; i < (EMBP - EMBD) * C1 / 4; i += 256)
        ((float4*)s_w)[EMBD * C1 / 4 + i] = make_float4(0.f, 0.f, 0.f, 0.f);
    __syncthreads();
    for (int i = t; i < 32 * EMBP; i += 256) {
        int n = i / EMBP, k = i % EMBP;
        float v = (k < EMBD) ? emb[(size_t)xs[n] * EMBD + k] : 0.f;
        s_h2[i * 2] = v; s_h2[i * 2 + 1] = v;
    }
    __syncthreads();
    int cg = t & 63, g = t >> 6;
    int c0 = cg * 4;
    float4 bv = *(const float4*)&bvec[c0];
    ulonglong2 acc[8];
#pragma unroll
    for (int j = 0; j < 8; j++) {
        acc[j].x = pack2(bv.x, bv.y);
        acc[j].y = pack2(bv.z, bv.w);
    }
#pragma unroll 4
    for (int k = 0; k < EMBP; k++) {
        ulonglong2 w = *(const ulonglong2*)&s_w[k * C1 + c0];
#pragma unroll
        for (int j = 0; j < 8; j++) {
            unsigned long long h2 =
                *(const unsigned long long*)&s_h2[((g * 8 + j) * EMBP + k) * 2];
            acc[j].x = fma2(h2, w.x, acc[j].x);
            acc[j].y = fma2(h2, w.y, acc[j].y);
        }
    }
    float* dst = sel ? g_xr : g_xl;
#pragma unroll
    for (int j = 0; j < 8; j++) {
        int n = nb + g * 8 + j;
        if (n < NN) {
            float2 lo = unpack2(acc[j].x), hi = unpack2(acc[j].y);
            *(float4*)&dst[(size_t)n * C1 + c0] = make_float4(lo.x, lo.y, hi.x, hi.y);
        }
    }
}

// edge logits L1, CSR order: writes exp(logit) and accumulates denominator
__global__ __launch_bounds__(256, 4) void k_edge1(const float* __restrict__ ea,
                                                  const float* __restrict__ We,
                                                  const float* __restrict__ att) {
    extern __shared__ float sm[];
    float* s_we  = sm;                      // 28*256 = 7168 floats
    float* s_ea2 = sm + 7168;               // 32*28*2 = 1792 floats
    __shared__ int s_src[TE], s_dst[TE], s_eid[TE];
    int t  = threadIdx.x;
    int eb = blockIdx.x * TE;
    if (t < TE) {
        int4 pk = g_epk[eb + t];
        s_eid[t] = pk.x;
        s_src[t] = pk.y;
        s_dst[t] = pk.z;
    }
    for (int i = t; i < ED * C1 / 4; i += 256)
        ((float4*)s_we)[i] = ((const float4*)We)[i];
    __syncthreads();
    for (int i = t; i < TE * ED; i += 256) {
        int e = i / ED, k = i - e * ED;
        float v = ea[(size_t)s_eid[e] * ED + k];
        s_ea2[i * 2] = v; s_ea2[i * 2 + 1] = v;
    }
    int cg = t & 63, eq = t >> 6;
    int c0 = cg * 4;
    ulonglong2 acc[8];
#pragma unroll
    for (int j = 0; j < 8; j++) {
        int e = eq * 8 + j;
        float4 a = *(const float4*)&g_xl[(size_t)s_src[e] * C1 + c0];
        float4 b = *(const float4*)&g_xr[(size_t)s_dst[e] * C1 + c0];
        acc[j].x = pack2(a.x + b.x, a.y + b.y);
        acc[j].y = pack2(a.z + b.z, a.w + b.w);
    }
    __syncthreads();
#pragma unroll 4
    for (int k = 0; k < ED; k++) {
        ulonglong2 w = *(const ulonglong2*)&s_we[k * C1 + c0];
#pragma unroll
        for (int j = 0; j < 8; j++) {
            unsigned long long e2 =
                *(const unsigned long long*)&s_ea2[((eq * 8 + j) * ED + k) * 2];
            acc[j].x = fma2(e2, w.x, acc[j].x);
            acc[j].y = fma2(e2, w.y, acc[j].y);
        }
    }
    float a0 = att[c0], a1 = att[c0 + 1], a2 = att[c0 + 2], a3 = att[c0 + 3];
    float part[8];
#pragma unroll
    for (int j = 0; j < 8; j++) {
        float2 lo = unpack2(acc[j].x), hi = unpack2(acc[j].y);
        part[j] = lrelu(lo.x) * a0 + lrelu(lo.y) * a1 +
                  lrelu(hi.x) * a2 + lrelu(hi.y) * a3;
    }
#pragma unroll
    for (int off = 8; off; off >>= 1) {
#pragma unroll
        for (int j = 0; j < 8; j++)
            part[j] += __shfl_down_sync(0xffffffffu, part[j], off);
    }
    int lane = t & 31;
    if ((lane & 15) == 0) {
        int h = cg >> 4;
#pragma unroll
        for (int j = 0; j < 8; j++) {
            int e = eq * 8 + j;
            float ex = expf(part[j]);
            g_logit[(size_t)(eb + e) * 4 + h] = ex;     // alpha numerator, CSR order
            atomicAdd(&g_den[s_dst[e] * 4 + h], ex);
        }
    }
}

// aggregation L1: 2 nodes/block, 2-way edge-split per node + fused LN stats
__global__ __launch_bounds__(256) void k_agg1(const float* __restrict__ bias) {
    __shared__ float s_part[2][C1];
    int t = threadIdx.x;
    int nloc = t >> 7;                 // 0..1
    int half = (t >> 6) & 1;           // edge-range half
    int t64 = t & 63;
    int lane = t & 31;
    int n = blockIdx.x * 2 + nloc;
    int c0 = t64 * 4;
    int h  = t64 >> 4;
    int s = g_off[n], en = g_off[n + 1];
    int mid = (s + en + 1) >> 1;
    int beg = half ? mid : s;
    int end = half ? en : mid;
    float4 acc = make_float4(0.f, 0.f, 0.f, 0.f);
    for (int p = beg; p < end; p++) {
        float ex = g_logit[(size_t)p * 4 + h];
        int src = g_epk[p].y;
        float4 v = *(const float4*)&g_xl[(size_t)src * C1 + c0];
        acc.x += ex * v.x; acc.y += ex * v.y;
        acc.z += ex * v.z; acc.w += ex * v.w;
    }
    if (half) *(float4*)&s_part[nloc][c0] = acc;
    __syncthreads();
    float4 o = make_float4(0.f, 0.f, 0.f, 0.f);
    if (!half) {
        float4 p2 = *(const float4*)&s_part[nloc][c0];
        acc.x += p2.x; acc.y += p2.y; acc.z += p2.z; acc.w += p2.w;
        float inv = 1.f / (g_den[n * 4 + h] + 1e-16f);
        float4 bv = *(const float4*)&bias[c0];
        o.x = acc.x * inv + bv.x; o.y = acc.y * inv + bv.y;
        o.z = acc.z * inv + bv.z; o.w = acc.w * inv + bv.w;
        *(float4*)&g_h1[(size_t)n * C1 + c0] = o;
    }
    float sv = o.x + o.y + o.z + o.w;
    float qv = o.x * o.x + o.y * o.y + o.z * o.z + o.w * o.w;
#pragma unroll
    for (int off = 16; off; off >>= 1) {
        sv += __shfl_down_sync(0xffffffffu, sv, off);
        qv += __shfl_down_sync(0xffffffffu, qv, off);
    }
    __shared__ double sh[8], qh[8];
    int w = t >> 5;
    if (lane == 0) { sh[w] = (double)sv; qh[w] = (double)qv; }
    __syncthreads();
    if (t == 0) {
        double S = 0.0, Q = 0.0;
        for (int i = 0; i < 8; i++) { S += sh[i]; Q += qh[i]; }
        atomicAdd(&g_red[0], S); atomicAdd(&g_red[1], Q);
    }
}

// node transform L2: fused LN1+ReLU, duplicated-h smem, f32x2
__global__ __launch_bounds__(256) void k_node2(const float* __restrict__ Wl,
                                               const float* __restrict__ bl,
                                               const float* __restrict__ Wr,
                                               const float* __restrict__ br,
                                               const float* __restrict__ lnw,
                                               const float* __restrict__ lnb) {
    __shared__ float hs2[16 * C1 * 2];
    __shared__ float s_lnw[C1], s_lnb[C1];
    __shared__ float s_mf[2];
    int t = threadIdx.x;
    int nb = blockIdx.x * 16;
    if (t < C1) { s_lnw[t] = lnw[t]; s_lnb[t] = lnb[t]; }
    if (t == 0) {
        double M = (double)NN * C1;
        double mean = g_red[0] / M;
        double var  = g_red[1] / M - mean * mean;
        s_mf[0] = (float)mean;
        s_mf[1] = 1.f / ((float)sqrt(var > 0.0 ? var : 0.0) + 1e-5f);
    }
    __syncthreads();
    float mean = s_mf[0], f = s_mf[1];
    for (int i = t; i < 16 * C1 / 4; i += 256) {
        float4 v = *(const float4*)&g_h1[(size_t)nb * C1 + (size_t)i * 4];
        int k = (i & 63) * 4;
        float4 w4 = *(const float4*)&s_lnw[k];
        float4 b4 = *(const float4*)&s_lnb[k];
        v.x = (v.x - mean) * f * w4.x + b4.x; v.x = v.x > 0.f ? v.x : 0.f;
        v.y = (v.y - mean) * f * w4.y + b4.y; v.y = v.y > 0.f ? v.y : 0.f;
        v.z = (v.z - mean) * f * w4.z + b4.z; v.z = v.z > 0.f ? v.z : 0.f;
        v.w = (v.w - mean) * f * w4.w + b4.w; v.w = v.w > 0.f ? v.w : 0.f;
        *(float4*)&hs2[i * 8]     = make_float4(v.x, v.x, v.y, v.y);
        *(float4*)&hs2[i * 8 + 4] = make_float4(v.z, v.z, v.w, v.w);
    }
    __syncthreads();
    int cp = t & 31;
    int c2 = cp * 2;
    int grp = t >> 5;
    int n0 = grp * 2, n1 = grp * 2 + 1;
    bool act = (c2 + 1) < C2;
    unsigned long long blv = 0, brv = 0;
    if (act) {
        blv = pack2(bl[c2], bl[c2 + 1]);
        brv = pack2(br[c2], br[c2 + 1]);
    }
    unsigned long long al0 = blv, al1 = blv, ar0 = brv, ar1 = brv;
#pragma unroll 4
    for (int k = 0; k < C1; k++) {
        unsigned long long wl = 0, wr = 0;
        if (act) {
            wl = *(const unsigned long long*)&Wl[k * C2 + c2];
            wr = *(const unsigned long long*)&Wr[k * C2 + c2];
        }
        unsigned long long h0 = *(const unsigned long long*)&hs2[(n0 * C1 + k) * 2];
        unsigned long long h1 = *(const unsigned long long*)&hs2[(n1 * C1 + k) * 2];
        al0 = fma2(h0, wl, al0);
        al1 = fma2(h1, wl, al1);
        ar0 = fma2(h0, wr, ar0);
        ar1 = fma2(h1, wr, ar1);
    }
    if (act) {
        float2 v;
        v = unpack2(al0); *(float2*)&g_xl[(size_t)(nb + n0) * C2 + c2] = v;
        v = unpack2(al1); *(float2*)&g_xl[(size_t)(nb + n1) * C2 + c2] = v;
        v = unpack2(ar0); *(float2*)&g_xr[(size_t)(nb + n0) * C2 + c2] = v;
        v = unpack2(ar1); *(float2*)&g_xr[(size_t)(nb + n1) * C2 + c2] = v;
    }
}

// edge logits L2, CSR order: block-tile, smem ea splats (no shfl chain), f32x2
__global__ __launch_bounds__(256, 4) void k_edge2(const float* __restrict__ ea,
                                                  const float* __restrict__ We,
                                                  const float* __restrict__ att) {
    __shared__ float s_we2[ED * 64];
    __shared__ float s_ea2[TE2 * ED * 2];
    __shared__ float s_att[64];
    __shared__ int s_src[TE2], s_dst[TE2], s_eid[TE2];
    int t = threadIdx.x;
    int eb = blockIdx.x * TE2;
    if (t < TE2) {
        int4 pk = g_epk[eb + t];
        s_eid[t] = pk.x;
        s_src[t] = pk.y;
        s_dst[t] = pk.z;
    }
    if (t < 64) s_att[t] = (t < C2) ? att[t] : 0.f;
    for (int i = t; i < ED * 64; i += 256) {
        int k = i >> 6, c = i & 63;
        s_we2[i] = (c < C2) ? We[k * C2 + c] : 0.f;
    }
    __syncthreads();
    for (int i = t; i < TE2 * ED; i += 256) {
        int e = i / ED, k = i - e * ED;
        float v = ea[(size_t)s_eid[e] * ED + k];
        s_ea2[i * 2] = v; s_ea2[i * 2 + 1] = v;
    }
    int cg = t & 31, eq = t >> 5;
    int c0 = cg * 2;
    bool act = c0 < C2;
    unsigned long long acc[4];
#pragma unroll
    for (int j = 0; j < 4; j++) {
        int e = eq * 4 + j;
        float mx = 0.f, my = 0.f;
        if (act) {
            float2 u = *(const float2*)&g_xl[(size_t)s_src[e] * C2 + c0];
            float2 v = *(const float2*)&g_xr[(size_t)s_dst[e] * C2 + c0];
            mx = u.x + v.x; my = u.y + v.y;
        }
        acc[j] = pack2(mx, my);
    }
    __syncthreads();
#pragma unroll 4
    for (int k = 0; k < ED; k++) {
        unsigned long long w2 = *(const unsigned long long*)&s_we2[k * 64 + c0];
#pragma unroll
        for (int j = 0; j < 4; j++) {
            unsigned long long e2 =
                *(const unsigned long long*)&s_ea2[((eq * 4 + j) * ED + k) * 2];
            acc[j] = fma2(e2, w2, acc[j]);
        }
    }
    float2 a2 = *(const float2*)&s_att[c0];
    float part[4];
#pragma unroll
    for (int j = 0; j < 4; j++) {
        float2 m = unpack2(acc[j]);
        part[j] = lrelu(m.x) * a2.x + lrelu(m.y) * a2.y;
    }
#pragma unroll
    for (int off = 16; off; off >>= 1) {
#pragma unroll
        for (int j = 0; j < 4; j++)
            part[j] += __shfl_down_sync(0xffffffffu, part[j], off);
    }
    if (cg == 0) {
#pragma unroll
        for (int j = 0; j < 4; j++) {
            int e = eq * 4 + j;
            float ex = expf(part[j]);
            g_logit[eb + e] = ex;
            atomicAdd(&g_den[4 * NN + s_dst[e]], ex);
        }
    }
}

// aggregation L2: pure weighted gather + fused LN stats
__global__ __launch_bounds__(256) void k_agg2(const float* __restrict__ bias) {
    int t = threadIdx.x;
    int n = blockIdx.x * 4 + (t >> 6);
    int t64 = t & 63;
    int lane = t & 31;
    int s = g_off[n], en = g_off[n + 1];
    bool act = t64 < C2;
    float acc = 0.f;
    for (int p = s; p < en; p++) {
        float ex = g_logit[p];
        int src = g_epk[p].y;
        if (act) acc += ex * g_xl[(size_t)src * C2 + t64];
    }
    float o = 0.f;
    if (act) {
        o = acc / (g_den[4 * NN + n] + 1e-16f) + bias[t64];
        g_o2[(size_t)n * C2 + t64] = o;
    }
    float sv = o, qv = o * o;
#pragma unroll
    for (int off = 16; off; off >>= 1) {
        sv += __shfl_down_sync(0xffffffffu, sv, off);
        qv += __shfl_down_sync(0xffffffffu, qv, off);
    }
    __shared__ double sh[8], qh[8];
    int w = t >> 5;
    if (lane == 0) { sh[w] = (double)sv; qh[w] = (double)qv; }
    __syncthreads();
    if (t == 0) {
        double S = 0.0, Q = 0.0;
        for (int i = 0; i < 8; i++) { S += sh[i]; Q += qh[i]; }
        atomicAdd(&g_red[2], S); atomicAdd(&g_red[3], Q);
    }
}

__global__ void k_ln2(float* __restrict__ out, const float* __restrict__ w,
                      const float* __restrict__ b) {
    int i = blockIdx.x * blockDim.x + threadIdx.x;
    if (i < NN * C2) {
        double M = (double)NN * C2;
        double mean = g_red[2] / M;
        double var  = g_red[3] / M - mean * mean;
        float f = 1.f / ((float)sqrt(var > 0.0 ? var : 0.0) + 1e-5f);
        int c = i % C2;
        out[i] = (g_o2[i] - (float)mean) * f * w[c] + b[c];
    }
}

extern "C" void kernel_launch(void* const* d_in, const int* in_sizes, int n_in,
                              void* d_out, int out_size) {
    const int*   x    = (const int*)d_in[0];
    const int*   ei   = (const int*)d_in[1];
    const float* ea   = (const float*)d_in[2];
    const float* emb  = (const float*)d_in[3];
    const float* Wl1  = (const float*)d_in[4];
    const float* bl1  = (const float*)d_in[5];
    const float* Wr1  = (const float*)d_in[6];
    const float* br1  = (const float*)d_in[7];
    const float* We1  = (const float*)d_in[8];
    const float* att1 = (const float*)d_in[9];
    const float* bias1= (const float*)d_in[10];
    const float* ln1w = (const float*)d_in[11];
    const float* ln1b = (const float*)d_in[12];
    const float* Wl2  = (const float*)d_in[13];
    const float* bl2  = (const float*)d_in[14];
    const float* Wr2  = (const float*)d_in[15];
    const float* br2  = (const float*)d_in[16];
    const float* We2  = (const float*)d_in[17];
    const float* att2 = (const float*)d_in[18];
    const float* bias2= (const float*)d_in[19];
    const float* ln2w = (const float*)d_in[20];
    const float* ln2b = (const float*)d_in[21];
    float* out = (float*)d_out;

    const int node1_smem = (EMBP * C1 + 32 * EMBP * 2) * 4;   // ~66.6 KB
    const int edge1_smem = (7168 + TE * ED * 2) * 4;          // ~35.8 KB
    const int scan_smem  = NN * 4;                            // 200 KB
    cudaFuncSetAttribute(k_node1, cudaFuncAttributeMaxDynamicSharedMemorySize, node1_smem);
    cudaFuncSetAttribute(k_edge1, cudaFuncAttributeMaxDynamicSharedMemorySize, edge1_smem);
    cudaFuncSetAttribute(k_scan,  cudaFuncAttributeMaxDynamicSharedMemorySize, scan_smem);

    dim3 n1grid((NN + 31) / 32, 2);

    k_init<<<(5 * NN + 255) / 256, 256>>>();                               // 1
    k_deg<<<(EE + 255) / 256, 256>>>(ei);                                  // 2
    k_scan<<<1, 1024, scan_smem>>>();                                      // 3
    k_node1<<<n1grid, 256, node1_smem>>>(x, emb, Wl1, bl1, Wr1, br1);      // 4
    k_fill<<<(EE + 255) / 256, 256>>>(ei);                                 // 5
    k_edge1<<<EE / TE, 256, edge1_smem>>>(ea, We1, att1);                  // 6
    k_agg1<<<NN / 2, 256>>>(bias1);                                        // 7
    k_node2<<<NN / 16, 256>>>(Wl2, bl2, Wr2, br2, ln1w, ln1b);             // 8
    k_edge2<<<EE / TE2, 256>>>(ea, We2, att2);                             // 9
    k_agg2<<<NN / 4, 256>>>(bias2);                                        // 10
    k_ln2<<<(NN * C2 + 255) / 256, 256>>>(out, ln2w, ln2b);                // 11
}